// round 3
// baseline (speedup 1.0000x reference)
#include <cuda_runtime.h>
#include <cstdint>

// Problem constants: x (8,512,64,64) f32, mask (64,64) i32, out (8,768,64,64) f32
#define HW      4096
#define BATCH   8
#define CIN     512
#define C2      256
#define COUT    768

// Scratch (allocation-free rule: __device__ globals)
__device__ int g_cols[HW];   // ascending list of unmasked columns
__device__ int g_m;          // count of unmasked columns
__device__ int g_nb[HW];     // argmax column per row
__device__ int g_sidx[HW];   // flag[i] ? nb[i] : -1

// ---------------------------------------------------------------------------
// threefry2x32 with key (0, 42), counters (x0=0, x1=c). JAX partitionable path:
// bits[i] = o0 ^ o1 with counter = i. ks = [0, 42, 0 ^ 42 ^ 0x1BD11BDA].
// ---------------------------------------------------------------------------
__device__ __forceinline__ void threefry_0_42(unsigned c, unsigned& o0, unsigned& o1) {
    const unsigned ks1 = 42u;
    const unsigned ks2 = 0x1BD11BDAu ^ 42u;   // 0x1BD11BF0
    unsigned x0 = 0u;          // counts_hi + ks0
    unsigned x1 = c + ks1;     // counts_lo + ks1
#define TF_RND(r) { x0 += x1; x1 = __funnelshift_l(x1, x1, (r)); x1 ^= x0; }
    TF_RND(13) TF_RND(15) TF_RND(26) TF_RND(6)
    x0 += ks1;  x1 += ks2 + 1u;
    TF_RND(17) TF_RND(29) TF_RND(16) TF_RND(24)
    x0 += ks2;  x1 += 0u  + 2u;
    TF_RND(13) TF_RND(15) TF_RND(26) TF_RND(6)
    x0 += 0u;   x1 += ks1 + 3u;
    TF_RND(17) TF_RND(29) TF_RND(16) TF_RND(24)
    x0 += ks1;  x1 += ks2 + 4u;
    TF_RND(13) TF_RND(15) TF_RND(26) TF_RND(6)
    x0 += ks2;  x1 += 0u  + 5u;
#undef TF_RND
    o0 = x0; o1 = x1;
}

// ---------------------------------------------------------------------------
// Kernel A: ordered compaction of unmasked column indices. 1 block, 1024 thr.
// ---------------------------------------------------------------------------
__global__ void __launch_bounds__(1024) compact_kernel(const int* __restrict__ mask) {
    __shared__ int tsum[1024];
    int tid = threadIdx.x;
    int base = tid * 4;
    int f[4]; int tot = 0;
#pragma unroll
    for (int k = 0; k < 4; k++) { f[k] = (mask[base + k] <= 0) ? 1 : 0; tot += f[k]; }
    tsum[tid] = tot;
    __syncthreads();
    // Hillis-Steele inclusive scan over 1024 thread totals
    for (int off = 1; off < 1024; off <<= 1) {
        int v = (tid >= off) ? tsum[tid - off] : 0;
        __syncthreads();
        tsum[tid] += v;
        __syncthreads();
    }
    int pos = tsum[tid] - tot;  // exclusive prefix
#pragma unroll
    for (int k = 0; k < 4; k++) {
        if (f[k]) g_cols[pos++] = base + k;
    }
    if (tid == 1023) g_m = tsum[1023];
}

// ---------------------------------------------------------------------------
// Kernel B: per-row masked argmax of the fixed uniform(key 42) matrix.
// One CTA per row. Column list staged in shared memory (<=16KB). Threads
// stride the ascending list, so strictly-greater update preserves the
// first-occurrence tie-break within a thread; cross-thread ties resolved by
// the packed (val<<12)|(4095-j) key in the reduction.
// ---------------------------------------------------------------------------
__global__ void __launch_bounds__(256) argmax_kernel() {
    __shared__ int scols[HW];
    __shared__ unsigned long long sk[256];

    const int m = g_m;
    for (int t = threadIdx.x; t < m; t += 256) scols[t] = g_cols[t];
    __syncthreads();

    const int row = blockIdx.x;
    const unsigned rowbase = (unsigned)row * (unsigned)HW;

    unsigned bv = 0u;
    int bj = HW - 1;   // phantom (val=0, j=4095): loses to every real candidate

    for (int t = threadIdx.x; t < m; t += 256) {
        int j = scols[t];
        unsigned o0, o1;
        threefry_0_42(rowbase + (unsigned)j, o0, o1);
        unsigned v = (o0 ^ o1) >> 9;   // monotone proxy for the uniform float
        if (v > bv) { bv = v; bj = j; }
    }

    sk[threadIdx.x] = ((unsigned long long)bv << 12) | (unsigned)(HW - 1 - bj);
    __syncthreads();
#pragma unroll
    for (int off = 128; off > 0; off >>= 1) {
        if (threadIdx.x < off) {
            unsigned long long a = sk[threadIdx.x], b = sk[threadIdx.x + off];
            sk[threadIdx.x] = (b > a) ? b : a;
        }
        __syncthreads();
    }
    if (threadIdx.x == 0) {
        g_nb[row] = (m == 0) ? 0 : (HW - 1 - (int)(sk[0] & 0xFFFu));
    }
}

// ---------------------------------------------------------------------------
// Kernel B2: fold mask into gather index (-1 = write zero).
// ---------------------------------------------------------------------------
__global__ void sidx_kernel(const int* __restrict__ mask) {
    int i = blockIdx.x * blockDim.x + threadIdx.x;
    if (i < HW) g_sidx[i] = (mask[i] > 0) ? g_nb[i] : -1;
}

// ---------------------------------------------------------------------------
// Kernel C: build the output. Plane p = b*768 + ch; ch<512 → straight copy,
// ch>=512 → masked gather from x channel (ch-256).
// ---------------------------------------------------------------------------
__global__ void __launch_bounds__(256) output_kernel(const float* __restrict__ x,
                                                     float* __restrict__ out) {
    const int plane = blockIdx.x;              // 0 .. 8*768-1
    const int b  = plane / COUT;
    const int ch = plane - b * COUT;
    float4* __restrict__ dst = (float4*)(out + (size_t)plane * HW);

    if (ch < CIN) {
        const float4* __restrict__ src =
            (const float4*)(x + ((size_t)b * CIN + ch) * HW);
#pragma unroll
        for (int k = 0; k < 4; k++) {
            int idx = threadIdx.x + k * 256;
            dst[idx] = src[idx];
        }
    } else {
        const float* __restrict__ src = x + ((size_t)b * CIN + (ch - C2)) * HW;
        const int4* __restrict__ sidx4 = (const int4*)g_sidx;
#pragma unroll
        for (int k = 0; k < 4; k++) {
            int idx = threadIdx.x + k * 256;
            int4 s = sidx4[idx];
            float4 v;
            v.x = (s.x >= 0) ? src[s.x] : 0.0f;
            v.y = (s.y >= 0) ? src[s.y] : 0.0f;
            v.z = (s.z >= 0) ? src[s.z] : 0.0f;
            v.w = (s.w >= 0) ? src[s.w] : 0.0f;
            dst[idx] = v;
        }
    }
}

// ---------------------------------------------------------------------------
extern "C" void kernel_launch(void* const* d_in, const int* in_sizes, int n_in,
                              void* d_out, int out_size) {
    const float* x    = (const float*)d_in[0];   // (8,512,64,64) f32
    const int*   mask = (const int*)d_in[1];     // (64,64) i32
    float* out = (float*)d_out;                  // (8,768,64,64) f32
    (void)in_sizes; (void)n_in; (void)out_size;

    compact_kernel<<<1, 1024>>>(mask);
    argmax_kernel<<<HW, 256>>>();
    sidx_kernel<<<(HW + 255) / 256, 256>>>(mask);
    output_kernel<<<BATCH * COUT, 256>>>(x, out);
}